// round 13
// baseline (speedup 1.0000x reference)
#include <cuda_runtime.h>
#include <cstdint>

#define Npts   20000
#define Msamp  5000
#define KNN    16
#define CIN    64
#define COUT   128
#define FDIM   (3 + CIN)          // 67
#define BN_EPS 1e-5f

// FPS: one 8-CTA cluster, flat warp-granular DSMEM exchange (R6 core)
#define FPS_CTAS    8
#define FT          256
#define FPS_WARPS   8
#define FPS_SLOTS   (FPS_CTAS * FPS_WARPS)    // 64
#define FPS_PPC     (Npts / FPS_CTAS)         // 2500
#define FPS_PPT     10
#define SLOT_BYTES  24
// tails
#define GM 2
#define KNN_QPW 2

// ---------------- device scratch (no allocs allowed) ----------------
__device__ float4   g_p4[Npts];
__device__ float4   g_q4[Msamp];
__device__ int      g_nidx[Msamp * KNN];
__device__ float    g_maxh[Msamp * COUT];
__device__ float    g_minh[Msamp * COUT];
__device__ float    g_ps [Msamp * COUT];
__device__ float    g_pss[Msamp * COUT];
__device__ float    g_mean[COUT];
__device__ float    g_rstd[COUT];
__device__ float    g_np_scratch[Msamp * 3];

// ---------------- PTX helpers ----------------
__device__ __forceinline__ uint32_t smem_u32(const void* p) {
    uint32_t a;
    asm("{ .reg .u64 t; cvta.to.shared.u64 t, %1; cvt.u32.u64 %0, t; }" : "=r"(a) : "l"(p));
    return a;
}
__device__ __forceinline__ uint32_t mapa_u32(uint32_t local_addr, uint32_t rank) {
    uint32_t r;
    asm("mapa.shared::cluster.u32 %0, %1, %2;" : "=r"(r) : "r"(local_addr), "r"(rank));
    return r;
}
__device__ __forceinline__ void st_async_u64(uint32_t raddr, unsigned long long v,
                                             uint32_t rmbar) {
    asm volatile("st.async.shared::cluster.mbarrier::complete_tx::bytes.b64 [%0], %1, [%2];"
                 :: "r"(raddr), "l"(v), "r"(rmbar) : "memory");
}
__device__ __forceinline__ void mbar_init(uint32_t mbar, uint32_t cnt) {
    asm volatile("mbarrier.init.shared.b64 [%0], %1;" :: "r"(mbar), "r"(cnt) : "memory");
}
__device__ __forceinline__ void mbar_expect_tx(uint32_t mbar, uint32_t bytes) {
    asm volatile("mbarrier.arrive.expect_tx.shared.b64 _, [%0], %1;"
                 :: "r"(mbar), "r"(bytes) : "memory");
}
// CTA-scope acquire: st.async delivers into LOCAL smem via the async proxy
// (same pattern as TMA); readers are local threads, so .acquire.cta suffices —
// this removes the cluster-scope fence from every per-iteration wait.
__device__ __forceinline__ void mbar_wait_parity(uint32_t mbar, uint32_t ph) {
    uint32_t done = 0;
    while (!done) {
        asm volatile(
            "{\n\t.reg .pred p;\n\t"
            "mbarrier.try_wait.parity.acquire.cta.shared::cta.b64 p, [%1], %2, 0x989680;\n\t"
            "selp.b32 %0, 1, 0, p;\n\t}"
            : "=r"(done) : "r"(mbar), "r"(ph) : "memory");
    }
}
__device__ __forceinline__ unsigned long long pack2f(float a, float b) {
    return ((unsigned long long)__float_as_uint(b) << 32) | __float_as_uint(a);
}

// slot argmax: winning slot index + key (all lanes), tie -> lowest global idx
__device__ __forceinline__ int slot_reduce(const unsigned long long* slots, int lane,
                                           unsigned long long& wkey) {
    unsigned long long v0 = slots[lane * 3];
    unsigned long long v1 = slots[(lane + 32) * 3];
    unsigned d0 = (unsigned)(v0 >> 15), d1 = (unsigned)(v1 >> 15);
    unsigned dg = __reduce_max_sync(0xFFFFFFFFu, d0 > d1 ? d0 : d1);
    unsigned l = 0;
    if (d0 == dg) l = (unsigned)v0 & 0x7FFFu;
    if (d1 == dg) { unsigned l1 = (unsigned)v1 & 0x7FFFu; if (l1 > l) l = l1; }
    unsigned lg = __reduce_max_sync(0xFFFFFFFFu, l);
    wkey = ((unsigned long long)dg << 15) | lg;
    unsigned b0 = __ballot_sync(0xFFFFFFFFu, v0 == wkey);
    int sl;
    if (b0) sl = __ffs(b0) - 1;
    else {
        unsigned b1 = __ballot_sync(0xFFFFFFFFu, v1 == wkey);
        sl = 32 + __ffs(b1) - 1;
    }
    return sl;
}

// ---------------- pack ----------------
__global__ void pack_kernel(const float* __restrict__ p) {
    int i = blockIdx.x * blockDim.x + threadIdx.x;
    if (i < Npts) {
        float x = p[3 * i], y = p[3 * i + 1], z = p[3 * i + 2];
        float pp = __fadd_rn(__fadd_rn(__fmul_rn(x, x), __fmul_rn(y, y)), __fmul_rn(z, z));
        g_p4[i] = make_float4(x, y, z, pp);
    }
}

// ---------------- FPS: 8-CTA cluster, flat exchange (R6 core; cta-scope waits) ----------------
__global__ void __cluster_dims__(FPS_CTAS, 1, 1) __launch_bounds__(FT, 1)
fps_kernel(float* __restrict__ out_np) {
    __shared__ unsigned long long s_slots[2][FPS_SLOTS * 3];   // key, xy, zw per slot
    __shared__ unsigned long long s_mbar[2];

    const int t = threadIdx.x, warp = t >> 5, lane = t & 31;
    uint32_t cta;
    asm("mov.u32 %0, %%cluster_ctarank;" : "=r"(cta));

    const uint32_t slot_base = smem_u32(&s_slots[0][0]);
    const uint32_t mbar_base = smem_u32(&s_mbar[0]);
    if (t == 0) { mbar_init(mbar_base, 1); mbar_init(mbar_base + 8, 1); }

    // register-resident slice
    float px[FPS_PPT], py[FPS_PPT], pz[FPS_PPT], pw[FPS_PPT], dist[FPS_PPT];
    unsigned gidx[FPS_PPT];
    bool valid[FPS_PPT];
#pragma unroll
    for (int j = 0; j < FPS_PPT; j++) {
        int li = t + j * FT;
        valid[j] = (li < FPS_PPC);
        int g = (int)cta * FPS_PPC + (valid[j] ? li : 0);
        float4 P = g_p4[g];
        px[j] = P.x; py[j] = P.y; pz[j] = P.z; pw[j] = P.w;
        dist[j] = 1e10f;
        gidx[j] = (unsigned)g;
    }
    const unsigned s_idx = cta * FPS_WARPS + (unsigned)warp;
    uint32_t rk[2] = {0, 0}, rm[2] = {0, 0};
    if (lane < FPS_CTAS) {
        uint32_t soff = s_idx * SLOT_BYTES;
        rk[0] = mapa_u32(slot_base + soff, (uint32_t)lane);
        rk[1] = mapa_u32(slot_base + FPS_SLOTS * SLOT_BYTES + soff, (uint32_t)lane);
        rm[0] = mapa_u32(mbar_base, (uint32_t)lane);
        rm[1] = mapa_u32(mbar_base + 8u, (uint32_t)lane);
    }

    asm volatile("barrier.cluster.arrive.aligned;" ::: "memory");
    asm volatile("barrier.cluster.wait.aligned;" ::: "memory");

    float lx, ly, lz;
    {
        float4 P0 = g_p4[0];
        lx = P0.x; ly = P0.y; lz = P0.z;
        if (cta == 0 && t == 0) g_q4[0] = P0;
        if (cta == 0 && t == 32) {
            out_np[0] = P0.x; out_np[1] = P0.y; out_np[2] = P0.z;
        }
    }
    unsigned ph0 = 0, ph1 = 0;

    for (int i = 1; i < Msamp; i++) {
        // --- update + per-thread argmax (uint order == float order, d>=0) ---
        unsigned bd = 0, bi = 0x7FFFFFFFu;
        float bx = 0.f, by = 0.f, bz = 0.f, bw = 0.f;
#pragma unroll
        for (int j = 0; j < FPS_PPT; j++) {
            float dx = __fsub_rn(px[j], lx);
            float dy = __fsub_rn(py[j], ly);
            float dz = __fsub_rn(pz[j], lz);
            float d  = __fadd_rn(__fadd_rn(__fmul_rn(dx, dx), __fmul_rn(dy, dy)),
                                 __fmul_rn(dz, dz));
            float nd = fminf(dist[j], d);
            dist[j] = nd;
            unsigned db = __float_as_uint(nd);
            if (valid[j] && db > bd) {
                bd = db; bi = gidx[j];
                bx = px[j]; by = py[j]; bz = pz[j]; bw = pw[j];
            }
        }
        unsigned dmax = __reduce_max_sync(0xFFFFFFFFu, bd);
        bool cand = (bd == dmax);
        unsigned idxmin = __reduce_min_sync(0xFFFFFFFFu, cand ? bi : 0xFFFFFFFFu);
        unsigned long long key =
            ((unsigned long long)dmax << 15) | ((32767u - idxmin) & 0x7FFFu);
        const int buf = i & 1;
        // winning lane broadcasts coords; lanes 0-7 ship triple to their CTA
        unsigned src_ballot = __ballot_sync(0xFFFFFFFFu, cand && bi == idxmin);
        int src = __ffs(src_ballot) - 1;
        float wx = __shfl_sync(0xFFFFFFFFu, bx, src);
        float wy = __shfl_sync(0xFFFFFFFFu, by, src);
        float wz = __shfl_sync(0xFFFFFFFFu, bz, src);
        float ww = __shfl_sync(0xFFFFFFFFu, bw, src);
        if (lane < FPS_CTAS) {
            uint32_t rs = rk[buf], rmm = rm[buf];
            st_async_u64(rs,      key,            rmm);
            st_async_u64(rs + 8,  pack2f(wx, wy), rmm);
            st_async_u64(rs + 16, pack2f(wz, ww), rmm);
        }
        if (t == 40)  // idle lane (warp 1, lane 8): keeps expect_tx off sender lanes
            mbar_expect_tx(mbar_base + 8u * (unsigned)buf, FPS_SLOTS * SLOT_BYTES);

        mbar_wait_parity(mbar_base + 8u * (unsigned)buf, buf ? ph1 : ph0);
        if (buf) ph1 ^= 1; else ph0 ^= 1;

        unsigned long long wkey;
        int sl = slot_reduce(s_slots[buf], lane, wkey);
        unsigned long long wxy = s_slots[buf][sl * 3 + 1];
        unsigned long long wzw = s_slots[buf][sl * 3 + 2];
        lx = __uint_as_float((unsigned)wxy);
        ly = __uint_as_float((unsigned)(wxy >> 32));
        lz = __uint_as_float((unsigned)wzw);
        if (cta == 0 && t == 0) {
            float w2 = __uint_as_float((unsigned)(wzw >> 32));
            g_q4[i] = make_float4(lx, ly, lz, w2);
        }
        if (cta == 0 && t == 32) {
            out_np[3 * i] = lx; out_np[3 * i + 1] = ly; out_np[3 * i + 2] = lz;
        }
    }
    // trailing cluster barrier: no CTA exits with peers' st.async in flight
    asm volatile("barrier.cluster.arrive.aligned;" ::: "memory");
    asm volatile("barrier.cluster.wait.aligned;" ::: "memory");
}

// ---------------- kNN: warp scans 2 queries per pass (half L2 traffic) ----------------
#define INFKEY 0xFFFFFFFFFFFFFFFFull

__device__ __forceinline__ void knn_merge(unsigned long long* cand, int lane,
                                          unsigned long long& cur,
                                          unsigned long long& thr, int& cnt) {
    if (lane < 16) cand[64 + lane] = cur;
#pragma unroll
    for (int s = lane; s < 64; s += 32) if (s >= cnt) cand[s] = INFKEY;
    __syncwarp();
    unsigned long long picked = INFKEY, last = INFKEY;
#pragma unroll 1
    for (int r = 0; r < 16; r++) {
        unsigned long long a = cand[lane];
        unsigned long long b = cand[lane + 32];
        unsigned long long c = (lane < 16) ? cand[64 + lane] : INFKEY;
        unsigned long long v = a < b ? a : b;
        v = v < c ? v : c;
#pragma unroll
        for (int off = 16; off; off >>= 1) {
            unsigned long long o = __shfl_down_sync(0xFFFFFFFFu, v, off);
            if (o < v) v = o;
        }
        v = __shfl_sync(0xFFFFFFFFu, v, 0);
        if (a == v)                       cand[lane]      = INFKEY;
        else if (b == v)                  cand[lane + 32] = INFKEY;
        else if (lane < 16 && c == v)     cand[64 + lane] = INFKEY;
        __syncwarp();
        if (lane == r) picked = v;
        last = v;
    }
    cur = picked; thr = last; cnt = 0;
    __syncwarp();
}

__global__ __launch_bounds__(128) void knn_kernel() {
    __shared__ unsigned long long cand_s[4][KNN_QPW][80];
    const int warp = threadIdx.x >> 5, lane = threadIdx.x & 31;
    const int m0 = (blockIdx.x * 4 + warp) * KNN_QPW;

    float4 Q0 = g_q4[m0], Q1 = g_q4[m0 + 1];
    unsigned long long cur0 = INFKEY, thr0 = INFKEY;
    unsigned long long cur1 = INFKEY, thr1 = INFKEY;
    int cnt0 = 0, cnt1 = 0;
    unsigned long long* c0 = cand_s[warp][0];
    unsigned long long* c1 = cand_s[warp][1];

#pragma unroll 1
    for (int s = 0; s < Npts / 32; s++) {
        int idx = lane + 32 * s;
        float4 P = __ldg(&g_p4[idx]);
        // reference: qq - 2*(q@p.T) + pp, dot as XLA fma chain (verified)
        float dot0 = __fmaf_rn(Q0.z, P.z, __fmaf_rn(Q0.y, P.y, __fmul_rn(Q0.x, P.x)));
        float d0 = __fadd_rn(__fsub_rn(Q0.w, __fmul_rn(2.0f, dot0)), P.w);
        float dot1 = __fmaf_rn(Q1.z, P.z, __fmaf_rn(Q1.y, P.y, __fmul_rn(Q1.x, P.x)));
        float d1 = __fadd_rn(__fsub_rn(Q1.w, __fmul_rn(2.0f, dot1)), P.w);
        unsigned u0 = __float_as_uint(d0);
        u0 ^= (u0 >> 31) ? 0xFFFFFFFFu : 0x80000000u;
        unsigned u1 = __float_as_uint(d1);
        u1 ^= (u1 >> 31) ? 0xFFFFFFFFu : 0x80000000u;
        unsigned long long k0 = ((unsigned long long)u0 << 32) | (unsigned)idx;
        unsigned long long k1 = ((unsigned long long)u1 << 32) | (unsigned)idx;

        bool p0 = k0 < thr0;
        unsigned b0 = __ballot_sync(0xFFFFFFFFu, p0);
        if (p0) c0[cnt0 + __popc(b0 & ((1u << lane) - 1u))] = k0;
        cnt0 += __popc(b0);
        if (cnt0 >= 32) knn_merge(c0, lane, cur0, thr0, cnt0);

        bool p1 = k1 < thr1;
        unsigned b1 = __ballot_sync(0xFFFFFFFFu, p1);
        if (p1) c1[cnt1 + __popc(b1 & ((1u << lane) - 1u))] = k1;
        cnt1 += __popc(b1);
        if (cnt1 >= 32) knn_merge(c1, lane, cur1, thr1, cnt1);
    }
    if (cnt0 > 0) knn_merge(c0, lane, cur0, thr0, cnt0);
    if (cnt1 > 0) knn_merge(c1, lane, cur1, thr1, cnt1);
    if (lane < 16) {
        g_nidx[m0 * KNN + lane]       = (int)(unsigned)(cur0 & 0xFFFFFFFFull);
        g_nidx[(m0 + 1) * KNN + lane] = (int)(unsigned)(cur1 & 0xFFFFFFFFull);
    }
}

// ---------------- gather + linear (GM samples/block); max/min of h + BN partials ----------------
__global__ __launch_bounds__(128) void gemm_kernel(const float* __restrict__ x,
                                                   const float* __restrict__ W) {
    __shared__ float sW[FDIM * COUT];
    __shared__ float sF[GM * KNN][FDIM + 1];
    const int m0 = blockIdx.x * GM, t = threadIdx.x;

    for (int i = t; i < FDIM * COUT; i += 128) sW[i] = W[i];
    for (int e = t; e < GM * KNN * FDIM; e += 128) {
        int mm = e / (KNN * FDIM);
        int rem = e - mm * (KNN * FDIM);
        int r = rem / FDIM, j = rem - r * FDIM;
        int m = m0 + mm;
        int n = g_nidx[m * KNN + r];
        float v;
        if (j < 3) {
            float4 P = g_p4[n];
            float4 Q = g_q4[m];
            v = (j == 0) ? __fsub_rn(P.x, Q.x) : (j == 1) ? __fsub_rn(P.y, Q.y)
                                                          : __fsub_rn(P.z, Q.z);
        } else {
            v = __ldg(&x[n * CIN + (j - 3)]);
        }
        sF[mm * KNN + r][j] = v;
    }
    __syncthreads();

#pragma unroll 1
    for (int mm = 0; mm < GM; mm++) {
        float acc[KNN];
#pragma unroll
        for (int r = 0; r < KNN; r++) acc[r] = 0.0f;
#pragma unroll 1
        for (int j = 0; j < FDIM; j++) {
            float wv = sW[j * COUT + t];
#pragma unroll
            for (int r = 0; r < KNN; r++)
                acc[r] = fmaf(sF[mm * KNN + r][j], wv, acc[r]);
        }
        float s1 = 0.0f, s2 = 0.0f;
        float mx = acc[0], mn = acc[0];
#pragma unroll
        for (int r = 0; r < KNN; r++) {
            s1 += acc[r];
            s2 = fmaf(acc[r], acc[r], s2);
            mx = fmaxf(mx, acc[r]);
            mn = fminf(mn, acc[r]);
        }
        const int m = m0 + mm;
        g_maxh[m * COUT + t] = mx;
        g_minh[m * COUT + t] = mn;
        g_ps [m * COUT + t] = s1;
        g_pss[m * COUT + t] = s2;
    }
}

// ---------------- deterministic BN stats reduction ----------------
__global__ __launch_bounds__(256) void stats_kernel() {
    __shared__ float s1[256], s2[256];
    const int c = blockIdx.x, t = threadIdx.x;
    float a = 0.0f, b = 0.0f;
    for (int m = t; m < Msamp; m += 256) {
        a += g_ps [m * COUT + c];
        b += g_pss[m * COUT + c];
    }
    s1[t] = a; s2[t] = b;
    __syncthreads();
    for (int o = 128; o; o >>= 1) {
        if (t < o) { s1[t] += s1[t + o]; s2[t] += s2[t + o]; }
        __syncthreads();
    }
    if (t == 0) {
        const float inv_n = 1.0f / (float)(Msamp * KNN);
        float mean = s1[0] * inv_n;
        float var  = fmaxf(s2[0] * inv_n - mean * mean, 0.0f);
        g_mean[c] = mean;
        g_rstd[c] = rsqrtf(var + BN_EPS);
    }
}

// ---------------- BN + ReLU + maxpool (exact via per-channel monotonicity) ----------------
__global__ __launch_bounds__(128) void final_kernel(const float* __restrict__ gamma,
                                                    const float* __restrict__ beta,
                                                    float* __restrict__ out_x,
                                                    float* __restrict__ out_no) {
    const int m = blockIdx.x, c = threadIdx.x;
    const float mean = g_mean[c], inv = g_rstd[c];
    const float gm = __ldg(&gamma[c]), bt = __ldg(&beta[c]);
    float h = (gm >= 0.0f) ? g_maxh[m * COUT + c] : g_minh[m * COUT + c];
    float y = fmaxf((h - mean) * inv * gm + bt, 0.0f);
    out_x[m * COUT + c] = y;
    if (out_no != nullptr && m == 0 && c == 0) *out_no = (float)Msamp;
}

// ---------------- launch ----------------
extern "C" void kernel_launch(void* const* d_in, const int* in_sizes, int n_in,
                              void* d_out, int out_size) {
    const float* p     = (const float*)d_in[0];
    const float* x     = (const float*)d_in[1];
    const float* W     = (const float*)d_in[3];
    const float* gamma = (const float*)d_in[4];
    const float* beta  = (const float*)d_in[5];
    float* out = (float*)d_out;

    const int np_elems = Msamp * 3;
    const int x_elems  = Msamp * COUT;

    float* np_dst = out;
    float* x_dst  = out + np_elems;
    float* no_dst = nullptr;
    if (out_size >= np_elems + x_elems + 1) {
        no_dst = out + np_elems + x_elems;
    } else if (out_size == x_elems) {
        float* scr; cudaGetSymbolAddress((void**)&scr, g_np_scratch);
        np_dst = scr;
        x_dst  = out;
    }

    pack_kernel <<<(Npts + 255) / 256, 256>>>(p);
    fps_kernel  <<<FPS_CTAS, FT>>>(np_dst);
    knn_kernel  <<<Msamp / (4 * KNN_QPW), 128>>>();
    gemm_kernel <<<Msamp / GM, 128>>>(x, W);
    stats_kernel<<<COUT, 256>>>();
    final_kernel<<<Msamp, 128>>>(gamma, beta, x_dst, no_dst);
}

// round 14
// speedup vs baseline: 1.0191x; 1.0191x over previous
#include <cuda_runtime.h>
#include <cstdint>

#define Npts   20000
#define Msamp  5000
#define KNN    16
#define CIN    64
#define COUT   128
#define FDIM   (3 + CIN)          // 67
#define BN_EPS 1e-5f

// FPS: one 8-CTA cluster, flat warp-granular DSMEM exchange (R6-verified, verbatim)
#define FPS_CTAS    8
#define FT          256
#define FPS_WARPS   8
#define FPS_SLOTS   (FPS_CTAS * FPS_WARPS)    // 64
#define FPS_PPC     (Npts / FPS_CTAS)         // 2500
#define FPS_PPT     10
#define SLOT_BYTES  24
// tails (verified)
#define GM 2
#define KNN_QPW 2

// ---------------- device scratch (no allocs allowed) ----------------
__device__ float4   g_p4[Npts];
__device__ float4   g_q4[Msamp];
__device__ int      g_nidx[Msamp * KNN];
__device__ float    g_maxh[Msamp * COUT];
__device__ float    g_minh[Msamp * COUT];
__device__ float    g_ps [Msamp * COUT];
__device__ float    g_pss[Msamp * COUT];
__device__ float    g_mean[COUT];
__device__ float    g_rstd[COUT];
__device__ float    g_np_scratch[Msamp * 3];

// ---------------- PTX helpers ----------------
__device__ __forceinline__ uint32_t smem_u32(const void* p) {
    uint32_t a;
    asm("{ .reg .u64 t; cvta.to.shared.u64 t, %1; cvt.u32.u64 %0, t; }" : "=r"(a) : "l"(p));
    return a;
}
__device__ __forceinline__ uint32_t mapa_u32(uint32_t local_addr, uint32_t rank) {
    uint32_t r;
    asm("mapa.shared::cluster.u32 %0, %1, %2;" : "=r"(r) : "r"(local_addr), "r"(rank));
    return r;
}
__device__ __forceinline__ void st_async_u64(uint32_t raddr, unsigned long long v,
                                             uint32_t rmbar) {
    asm volatile("st.async.shared::cluster.mbarrier::complete_tx::bytes.b64 [%0], %1, [%2];"
                 :: "r"(raddr), "l"(v), "r"(rmbar) : "memory");
}
__device__ __forceinline__ void mbar_init(uint32_t mbar, uint32_t cnt) {
    asm volatile("mbarrier.init.shared.b64 [%0], %1;" :: "r"(mbar), "r"(cnt) : "memory");
}
__device__ __forceinline__ void mbar_expect_tx(uint32_t mbar, uint32_t bytes) {
    asm volatile("mbarrier.arrive.expect_tx.shared.b64 _, [%0], %1;"
                 :: "r"(mbar), "r"(bytes) : "memory");
}
// R6-verified wait (cluster-scope acquire)
__device__ __forceinline__ void mbar_wait_parity(uint32_t mbar, uint32_t ph) {
    uint32_t done = 0;
    while (!done) {
        asm volatile(
            "{\n\t.reg .pred p;\n\t"
            "mbarrier.try_wait.parity.acquire.cluster.shared::cta.b64 p, [%1], %2, 0x989680;\n\t"
            "selp.b32 %0, 1, 0, p;\n\t}"
            : "=r"(done) : "r"(mbar), "r"(ph) : "memory");
    }
}
__device__ __forceinline__ unsigned long long pack2f(float a, float b) {
    return ((unsigned long long)__float_as_uint(b) << 32) | __float_as_uint(a);
}

// slot argmax: winning slot index + key (all lanes), tie -> lowest global idx
__device__ __forceinline__ int slot_reduce(const unsigned long long* slots, int lane,
                                           unsigned long long& wkey) {
    unsigned long long v0 = slots[lane * 3];
    unsigned long long v1 = slots[(lane + 32) * 3];
    unsigned d0 = (unsigned)(v0 >> 15), d1 = (unsigned)(v1 >> 15);
    unsigned dg = __reduce_max_sync(0xFFFFFFFFu, d0 > d1 ? d0 : d1);
    unsigned l = 0;
    if (d0 == dg) l = (unsigned)v0 & 0x7FFFu;
    if (d1 == dg) { unsigned l1 = (unsigned)v1 & 0x7FFFu; if (l1 > l) l = l1; }
    unsigned lg = __reduce_max_sync(0xFFFFFFFFu, l);
    wkey = ((unsigned long long)dg << 15) | lg;
    unsigned b0 = __ballot_sync(0xFFFFFFFFu, v0 == wkey);
    int sl;
    if (b0) sl = __ffs(b0) - 1;
    else {
        unsigned b1 = __ballot_sync(0xFFFFFFFFu, v1 == wkey);
        sl = 32 + __ffs(b1) - 1;
    }
    return sl;
}

// ---------------- pack ----------------
__global__ void pack_kernel(const float* __restrict__ p) {
    int i = blockIdx.x * blockDim.x + threadIdx.x;
    if (i < Npts) {
        float x = p[3 * i], y = p[3 * i + 1], z = p[3 * i + 2];
        float pp = __fadd_rn(__fadd_rn(__fmul_rn(x, x), __fmul_rn(y, y)), __fmul_rn(z, z));
        g_p4[i] = make_float4(x, y, z, pp);
    }
}

// ---------------- FPS: 8-CTA cluster, R6-verified core (verbatim) ----------------
__global__ void __cluster_dims__(FPS_CTAS, 1, 1) __launch_bounds__(FT, 1)
fps_kernel(float* __restrict__ out_np) {
    __shared__ unsigned long long s_slots[2][FPS_SLOTS * 3];   // key, xy, zw per slot
    __shared__ unsigned long long s_mbar[2];

    const int t    = threadIdx.x;
    const int warp = t >> 5, lane = t & 31;
    uint32_t cta;
    asm("mov.u32 %0, %%cluster_ctarank;" : "=r"(cta));
    const int base = (int)cta * FPS_PPC;

    // register-resident slice
    float px[FPS_PPT], py[FPS_PPT], pz[FPS_PPT], pw[FPS_PPT], dist[FPS_PPT];
    unsigned gidx[FPS_PPT];
    bool valid[FPS_PPT];
#pragma unroll
    for (int j = 0; j < FPS_PPT; j++) {
        int li = t + j * FT;
        valid[j] = (li < FPS_PPC);
        int g = base + (valid[j] ? li : 0);
        float4 P = g_p4[g];
        px[j] = P.x; py[j] = P.y; pz[j] = P.z; pw[j] = P.w;
        dist[j] = 1e10f;
        gidx[j] = (unsigned)g;
    }

    const uint32_t slot_base = smem_u32(&s_slots[0][0]);
    const uint32_t mbar_base = smem_u32(&s_mbar[0]);
    if (t == 0) { mbar_init(mbar_base, 1); mbar_init(mbar_base + 8, 1); }

    // remote addresses for senders (lanes 0-7 -> one CTA each)
    const unsigned s_idx = cta * FPS_WARPS + (unsigned)warp;
    uint32_t rk[2] = {0, 0}, rm[2] = {0, 0};
    if (lane < FPS_CTAS) {
        uint32_t soff = s_idx * SLOT_BYTES;
        rk[0] = mapa_u32(slot_base + soff, (uint32_t)lane);
        rk[1] = mapa_u32(slot_base + FPS_SLOTS * SLOT_BYTES + soff, (uint32_t)lane);
        rm[0] = mapa_u32(mbar_base, (uint32_t)lane);
        rm[1] = mapa_u32(mbar_base + 8u, (uint32_t)lane);
    }

    asm volatile("barrier.cluster.arrive.aligned;" ::: "memory");
    asm volatile("barrier.cluster.wait.aligned;" ::: "memory");

    float lx, ly, lz;
    {
        float4 P0 = g_p4[0];
        lx = P0.x; ly = P0.y; lz = P0.z;
        if (cta == 0 && t == 0) {
            out_np[0] = P0.x; out_np[1] = P0.y; out_np[2] = P0.z;
            g_q4[0] = P0;
        }
    }

    unsigned ph0 = 0, ph1 = 0;

    for (int i = 1; i < Msamp; i++) {
        // --- update dists, per-thread argmax (uint order == float order, d>=0) ---
        unsigned bd = 0, bi = 0x7FFFFFFFu;
        float bx = 0.f, by = 0.f, bz = 0.f, bw = 0.f;
#pragma unroll
        for (int j = 0; j < FPS_PPT; j++) {
            float dx = __fsub_rn(px[j], lx);
            float dy = __fsub_rn(py[j], ly);
            float dz = __fsub_rn(pz[j], lz);
            float d  = __fadd_rn(__fadd_rn(__fmul_rn(dx, dx), __fmul_rn(dy, dy)),
                                 __fmul_rn(dz, dz));
            float nd = fminf(dist[j], d);
            dist[j] = nd;
            unsigned db = __float_as_uint(nd);
            if (valid[j] && db > bd) {            // strict > keeps lowest idx in-thread
                bd = db; bi = gidx[j];
                bx = px[j]; by = py[j]; bz = pz[j]; bw = pw[j];
            }
        }
        // --- warp argmax via redux: max dist, tie -> min global index ---
        unsigned dmax = __reduce_max_sync(0xFFFFFFFFu, bd);
        bool cand = (bd == dmax);
        unsigned idxmin = __reduce_min_sync(0xFFFFFFFFu, cand ? bi : 0xFFFFFFFFu);
        unsigned long long key =
            ((unsigned long long)dmax << 15) | (unsigned)((32767u - idxmin) & 0x7FFFu);

        const int buf = i & 1;
        // winning lane broadcasts coords through shfl
        unsigned src_ballot = __ballot_sync(0xFFFFFFFFu, cand && bi == idxmin);
        int src = __ffs(src_ballot) - 1;
        float wx = __shfl_sync(0xFFFFFFFFu, bx, src);
        float wy = __shfl_sync(0xFFFFFFFFu, by, src);
        float wz = __shfl_sync(0xFFFFFFFFu, bz, src);
        float ww = __shfl_sync(0xFFFFFFFFu, bw, src);

        if (lane < FPS_CTAS) {
            uint32_t rs = rk[buf], rmm = rm[buf];
            st_async_u64(rs,      key,            rmm);
            st_async_u64(rs + 8,  pack2f(wx, wy), rmm);
            st_async_u64(rs + 16, pack2f(wz, ww), rmm);
        }
        if (t == 0)
            mbar_expect_tx(mbar_base + 8u * (unsigned)buf,
                           FPS_SLOTS * SLOT_BYTES);

        // --- wait for all 64 slot triplets ---
        unsigned myph = buf ? ph1 : ph0;
        mbar_wait_parity(mbar_base + 8u * (unsigned)buf, myph);
        if (buf) ph1 ^= 1; else ph0 ^= 1;

        // --- cross-slot argmax on keys ---
        unsigned long long wkey;
        int sl = slot_reduce(s_slots[buf], lane, wkey);
        unsigned long long wxy = s_slots[buf][sl * 3 + 1];
        unsigned long long wzw = s_slots[buf][sl * 3 + 2];
        lx = __uint_as_float((unsigned)wxy);
        ly = __uint_as_float((unsigned)(wxy >> 32));
        lz = __uint_as_float((unsigned)wzw);
        if (cta == 0 && t == 0) {
            float w = __uint_as_float((unsigned)(wzw >> 32));
            out_np[3 * i] = lx; out_np[3 * i + 1] = ly; out_np[3 * i + 2] = lz;
            g_q4[i] = make_float4(lx, ly, lz, w);
        }
    }
    // trailing cluster barrier: no CTA exits with peers' st.async in flight
    asm volatile("barrier.cluster.arrive.aligned;" ::: "memory");
    asm volatile("barrier.cluster.wait.aligned;" ::: "memory");
}

// ---------------- kNN: warp scans 2 queries per pass (half L2 traffic; verified) ----------------
#define INFKEY 0xFFFFFFFFFFFFFFFFull

__device__ __forceinline__ void knn_merge(unsigned long long* cand, int lane,
                                          unsigned long long& cur,
                                          unsigned long long& thr, int& cnt) {
    if (lane < 16) cand[64 + lane] = cur;
#pragma unroll
    for (int s = lane; s < 64; s += 32) if (s >= cnt) cand[s] = INFKEY;
    __syncwarp();
    unsigned long long picked = INFKEY, last = INFKEY;
#pragma unroll 1
    for (int r = 0; r < 16; r++) {
        unsigned long long a = cand[lane];
        unsigned long long b = cand[lane + 32];
        unsigned long long c = (lane < 16) ? cand[64 + lane] : INFKEY;
        unsigned long long v = a < b ? a : b;
        v = v < c ? v : c;
#pragma unroll
        for (int off = 16; off; off >>= 1) {
            unsigned long long o = __shfl_down_sync(0xFFFFFFFFu, v, off);
            if (o < v) v = o;
        }
        v = __shfl_sync(0xFFFFFFFFu, v, 0);
        if (a == v)                       cand[lane]      = INFKEY;
        else if (b == v)                  cand[lane + 32] = INFKEY;
        else if (lane < 16 && c == v)     cand[64 + lane] = INFKEY;
        __syncwarp();
        if (lane == r) picked = v;
        last = v;
    }
    cur = picked; thr = last; cnt = 0;
    __syncwarp();
}

__global__ __launch_bounds__(128) void knn_kernel() {
    __shared__ unsigned long long cand_s[4][KNN_QPW][80];
    const int warp = threadIdx.x >> 5, lane = threadIdx.x & 31;
    const int m0 = (blockIdx.x * 4 + warp) * KNN_QPW;

    float4 Q0 = g_q4[m0], Q1 = g_q4[m0 + 1];
    unsigned long long cur0 = INFKEY, thr0 = INFKEY;
    unsigned long long cur1 = INFKEY, thr1 = INFKEY;
    int cnt0 = 0, cnt1 = 0;
    unsigned long long* c0 = cand_s[warp][0];
    unsigned long long* c1 = cand_s[warp][1];

#pragma unroll 1
    for (int s = 0; s < Npts / 32; s++) {
        int idx = lane + 32 * s;
        float4 P = __ldg(&g_p4[idx]);
        // reference: qq - 2*(q@p.T) + pp, dot as XLA fma chain (verified)
        float dot0 = __fmaf_rn(Q0.z, P.z, __fmaf_rn(Q0.y, P.y, __fmul_rn(Q0.x, P.x)));
        float d0 = __fadd_rn(__fsub_rn(Q0.w, __fmul_rn(2.0f, dot0)), P.w);
        float dot1 = __fmaf_rn(Q1.z, P.z, __fmaf_rn(Q1.y, P.y, __fmul_rn(Q1.x, P.x)));
        float d1 = __fadd_rn(__fsub_rn(Q1.w, __fmul_rn(2.0f, dot1)), P.w);
        unsigned u0 = __float_as_uint(d0);
        u0 ^= (u0 >> 31) ? 0xFFFFFFFFu : 0x80000000u;
        unsigned u1 = __float_as_uint(d1);
        u1 ^= (u1 >> 31) ? 0xFFFFFFFFu : 0x80000000u;
        unsigned long long k0 = ((unsigned long long)u0 << 32) | (unsigned)idx;
        unsigned long long k1 = ((unsigned long long)u1 << 32) | (unsigned)idx;

        bool p0 = k0 < thr0;
        unsigned b0 = __ballot_sync(0xFFFFFFFFu, p0);
        if (p0) c0[cnt0 + __popc(b0 & ((1u << lane) - 1u))] = k0;
        cnt0 += __popc(b0);
        if (cnt0 >= 32) knn_merge(c0, lane, cur0, thr0, cnt0);

        bool p1 = k1 < thr1;
        unsigned b1 = __ballot_sync(0xFFFFFFFFu, p1);
        if (p1) c1[cnt1 + __popc(b1 & ((1u << lane) - 1u))] = k1;
        cnt1 += __popc(b1);
        if (cnt1 >= 32) knn_merge(c1, lane, cur1, thr1, cnt1);
    }
    if (cnt0 > 0) knn_merge(c0, lane, cur0, thr0, cnt0);
    if (cnt1 > 0) knn_merge(c1, lane, cur1, thr1, cnt1);
    if (lane < 16) {
        g_nidx[m0 * KNN + lane]       = (int)(unsigned)(cur0 & 0xFFFFFFFFull);
        g_nidx[(m0 + 1) * KNN + lane] = (int)(unsigned)(cur1 & 0xFFFFFFFFull);
    }
}

// ---------------- gather + linear (GM samples/block); max/min of h + BN partials ----------------
__global__ __launch_bounds__(128) void gemm_kernel(const float* __restrict__ x,
                                                   const float* __restrict__ W) {
    __shared__ float sW[FDIM * COUT];
    __shared__ float sF[GM * KNN][FDIM + 1];
    const int m0 = blockIdx.x * GM, t = threadIdx.x;

    for (int i = t; i < FDIM * COUT; i += 128) sW[i] = W[i];
    for (int e = t; e < GM * KNN * FDIM; e += 128) {
        int mm = e / (KNN * FDIM);
        int rem = e - mm * (KNN * FDIM);
        int r = rem / FDIM, j = rem - r * FDIM;
        int m = m0 + mm;
        int n = g_nidx[m * KNN + r];
        float v;
        if (j < 3) {
            float4 P = g_p4[n];
            float4 Q = g_q4[m];
            v = (j == 0) ? __fsub_rn(P.x, Q.x) : (j == 1) ? __fsub_rn(P.y, Q.y)
                                                          : __fsub_rn(P.z, Q.z);
        } else {
            v = __ldg(&x[n * CIN + (j - 3)]);
        }
        sF[mm * KNN + r][j] = v;
    }
    __syncthreads();

#pragma unroll 1
    for (int mm = 0; mm < GM; mm++) {
        float acc[KNN];
#pragma unroll
        for (int r = 0; r < KNN; r++) acc[r] = 0.0f;
#pragma unroll 1
        for (int j = 0; j < FDIM; j++) {
            float wv = sW[j * COUT + t];
#pragma unroll
            for (int r = 0; r < KNN; r++)
                acc[r] = fmaf(sF[mm * KNN + r][j], wv, acc[r]);
        }
        float s1 = 0.0f, s2 = 0.0f;
        float mx = acc[0], mn = acc[0];
#pragma unroll
        for (int r = 0; r < KNN; r++) {
            s1 += acc[r];
            s2 = fmaf(acc[r], acc[r], s2);
            mx = fmaxf(mx, acc[r]);
            mn = fminf(mn, acc[r]);
        }
        const int m = m0 + mm;
        g_maxh[m * COUT + t] = mx;
        g_minh[m * COUT + t] = mn;
        g_ps [m * COUT + t] = s1;
        g_pss[m * COUT + t] = s2;
    }
}

// ---------------- deterministic BN stats reduction ----------------
__global__ __launch_bounds__(256) void stats_kernel() {
    __shared__ float s1[256], s2[256];
    const int c = blockIdx.x, t = threadIdx.x;
    float a = 0.0f, b = 0.0f;
    for (int m = t; m < Msamp; m += 256) {
        a += g_ps [m * COUT + c];
        b += g_pss[m * COUT + c];
    }
    s1[t] = a; s2[t] = b;
    __syncthreads();
    for (int o = 128; o; o >>= 1) {
        if (t < o) { s1[t] += s1[t + o]; s2[t] += s2[t + o]; }
        __syncthreads();
    }
    if (t == 0) {
        const float inv_n = 1.0f / (float)(Msamp * KNN);
        float mean = s1[0] * inv_n;
        float var  = fmaxf(s2[0] * inv_n - mean * mean, 0.0f);
        g_mean[c] = mean;
        g_rstd[c] = rsqrtf(var + BN_EPS);
    }
}

// ---------------- BN + ReLU + maxpool (exact via per-channel monotonicity) ----------------
__global__ __launch_bounds__(128) void final_kernel(const float* __restrict__ gamma,
                                                    const float* __restrict__ beta,
                                                    float* __restrict__ out_x,
                                                    float* __restrict__ out_no) {
    const int m = blockIdx.x, c = threadIdx.x;
    const float mean = g_mean[c], inv = g_rstd[c];
    const float gm = __ldg(&gamma[c]), bt = __ldg(&beta[c]);
    float h = (gm >= 0.0f) ? g_maxh[m * COUT + c] : g_minh[m * COUT + c];
    float y = fmaxf((h - mean) * inv * gm + bt, 0.0f);
    out_x[m * COUT + c] = y;
    if (out_no != nullptr && m == 0 && c == 0) *out_no = (float)Msamp;
}

// ---------------- launch ----------------
extern "C" void kernel_launch(void* const* d_in, const int* in_sizes, int n_in,
                              void* d_out, int out_size) {
    const float* p     = (const float*)d_in[0];
    const float* x     = (const float*)d_in[1];
    const float* W     = (const float*)d_in[3];
    const float* gamma = (const float*)d_in[4];
    const float* beta  = (const float*)d_in[5];
    float* out = (float*)d_out;

    const int np_elems = Msamp * 3;
    const int x_elems  = Msamp * COUT;

    float* np_dst = out;
    float* x_dst  = out + np_elems;
    float* no_dst = nullptr;
    if (out_size >= np_elems + x_elems + 1) {
        no_dst = out + np_elems + x_elems;
    } else if (out_size == x_elems) {
        float* scr; cudaGetSymbolAddress((void**)&scr, g_np_scratch);
        np_dst = scr;
        x_dst  = out;
    }

    pack_kernel <<<(Npts + 255) / 256, 256>>>(p);
    fps_kernel  <<<FPS_CTAS, FT>>>(np_dst);
    knn_kernel  <<<Msamp / (4 * KNN_QPW), 128>>>();
    gemm_kernel <<<Msamp / GM, 128>>>(x, W);
    stats_kernel<<<COUT, 256>>>();
    final_kernel<<<Msamp, 128>>>(gamma, beta, x_dst, no_dst);
}

// round 15
// speedup vs baseline: 1.0828x; 1.0625x over previous
#include <cuda_runtime.h>
#include <cstdint>

#define Npts   20000
#define Msamp  5000
#define KNN    16
#define CIN    64
#define COUT   128
#define FDIM   (3 + CIN)          // 67
#define BN_EPS 1e-5f

// FPS: one 8-CTA cluster, flat warp-granular DSMEM exchange (R6-verified comm)
#define FPS_CTAS    8
#define FT          256
#define FPS_WARPS   8
#define FPS_SLOTS   (FPS_CTAS * FPS_WARPS)    // 64
#define FPS_PPC     (Npts / FPS_CTAS)         // 2500
#define FPS_PPT     10
#define SLOT_BYTES  24
// tails (verified)
#define GM 2
#define KNN_QPW 2

// ---------------- device scratch (no allocs allowed) ----------------
__device__ float4   g_p4[Npts];
__device__ float4   g_q4[Msamp];
__device__ int      g_nidx[Msamp * KNN];
__device__ float    g_maxh[Msamp * COUT];
__device__ float    g_minh[Msamp * COUT];
__device__ float    g_ps [Msamp * COUT];
__device__ float    g_pss[Msamp * COUT];
__device__ float    g_mean[COUT];
__device__ float    g_rstd[COUT];
__device__ float    g_np_scratch[Msamp * 3];

// ---------------- PTX helpers ----------------
__device__ __forceinline__ uint32_t smem_u32(const void* p) {
    uint32_t a;
    asm("{ .reg .u64 t; cvta.to.shared.u64 t, %1; cvt.u32.u64 %0, t; }" : "=r"(a) : "l"(p));
    return a;
}
__device__ __forceinline__ uint32_t mapa_u32(uint32_t local_addr, uint32_t rank) {
    uint32_t r;
    asm("mapa.shared::cluster.u32 %0, %1, %2;" : "=r"(r) : "r"(local_addr), "r"(rank));
    return r;
}
__device__ __forceinline__ void st_async_u64(uint32_t raddr, unsigned long long v,
                                             uint32_t rmbar) {
    asm volatile("st.async.shared::cluster.mbarrier::complete_tx::bytes.b64 [%0], %1, [%2];"
                 :: "r"(raddr), "l"(v), "r"(rmbar) : "memory");
}
__device__ __forceinline__ void mbar_init(uint32_t mbar, uint32_t cnt) {
    asm volatile("mbarrier.init.shared.b64 [%0], %1;" :: "r"(mbar), "r"(cnt) : "memory");
}
__device__ __forceinline__ void mbar_expect_tx(uint32_t mbar, uint32_t bytes) {
    asm volatile("mbarrier.arrive.expect_tx.shared.b64 _, [%0], %1;"
                 :: "r"(mbar), "r"(bytes) : "memory");
}
__device__ __forceinline__ void mbar_wait_parity(uint32_t mbar, uint32_t ph) {
    uint32_t done = 0;
    while (!done) {
        asm volatile(
            "{\n\t.reg .pred p;\n\t"
            "mbarrier.try_wait.parity.acquire.cluster.shared::cta.b64 p, [%1], %2, 0x989680;\n\t"
            "selp.b32 %0, 1, 0, p;\n\t}"
            : "=r"(done) : "r"(mbar), "r"(ph) : "memory");
    }
}
__device__ __forceinline__ unsigned long long pack2f(float a, float b) {
    return ((unsigned long long)__float_as_uint(b) << 32) | __float_as_uint(a);
}
// Blackwell packed f32x2 (IEEE rn per element — bit-identical to scalar)
__device__ __forceinline__ unsigned long long f2_add(unsigned long long a,
                                                     unsigned long long b) {
    unsigned long long r;
    asm("add.rn.f32x2 %0, %1, %2;" : "=l"(r) : "l"(a), "l"(b));
    return r;
}
__device__ __forceinline__ unsigned long long f2_mul(unsigned long long a,
                                                     unsigned long long b) {
    unsigned long long r;
    asm("mul.rn.f32x2 %0, %1, %2;" : "=l"(r) : "l"(a), "l"(b));
    return r;
}

// slot argmax: winning slot index + key (all lanes), tie -> lowest global idx
__device__ __forceinline__ int slot_reduce(const unsigned long long* slots, int lane,
                                           unsigned long long& wkey) {
    unsigned long long v0 = slots[lane * 3];
    unsigned long long v1 = slots[(lane + 32) * 3];
    unsigned d0 = (unsigned)(v0 >> 15), d1 = (unsigned)(v1 >> 15);
    unsigned dg = __reduce_max_sync(0xFFFFFFFFu, d0 > d1 ? d0 : d1);
    unsigned l = 0;
    if (d0 == dg) l = (unsigned)v0 & 0x7FFFu;
    if (d1 == dg) { unsigned l1 = (unsigned)v1 & 0x7FFFu; if (l1 > l) l = l1; }
    unsigned lg = __reduce_max_sync(0xFFFFFFFFu, l);
    wkey = ((unsigned long long)dg << 15) | lg;
    unsigned b0 = __ballot_sync(0xFFFFFFFFu, v0 == wkey);
    int sl;
    if (b0) sl = __ffs(b0) - 1;
    else {
        unsigned b1 = __ballot_sync(0xFFFFFFFFu, v1 == wkey);
        sl = 32 + __ffs(b1) - 1;
    }
    return sl;
}

// ---------------- pack ----------------
__global__ void pack_kernel(const float* __restrict__ p) {
    int i = blockIdx.x * blockDim.x + threadIdx.x;
    if (i < Npts) {
        float x = p[3 * i], y = p[3 * i + 1], z = p[3 * i + 2];
        float pp = __fadd_rn(__fadd_rn(__fmul_rn(x, x), __fmul_rn(y, y)), __fmul_rn(z, z));
        g_p4[i] = make_float4(x, y, z, pp);
    }
}

// ---------------- FPS: R6 exchange + packed-f32x2 update + L1-broadcast coords ----------------
__global__ void __cluster_dims__(FPS_CTAS, 1, 1) __launch_bounds__(FT, 1)
fps_kernel(float* __restrict__ out_np) {
    __shared__ unsigned long long s_slots[2][FPS_SLOTS * 3];   // key, xy, zw per slot
    __shared__ unsigned long long s_mbar[2];

    const int t    = threadIdx.x;
    const int warp = t >> 5, lane = t & 31;
    uint32_t cta;
    asm("mov.u32 %0, %%cluster_ctarank;" : "=r"(cta));
    const int base = (int)cta * FPS_PPC;
    const unsigned C = (unsigned)(base + t);          // gidx_j = C + j*FT

    // load slice, pack coords in pairs (j even/odd)
    unsigned long long px2[FPS_PPT / 2], py2[FPS_PPT / 2], pz2[FPS_PPT / 2];
    float dist[FPS_PPT];
    {
        float sx[FPS_PPT], sy[FPS_PPT], sz[FPS_PPT];
#pragma unroll
        for (int j = 0; j < FPS_PPT; j++) {
            int li = t + j * FT;
            int g = base + (li < FPS_PPC ? li : 0);
            float4 P = g_p4[g];
            sx[j] = P.x; sy[j] = P.y; sz[j] = P.z;
            dist[j] = 1e10f;
        }
#pragma unroll
        for (int k = 0; k < FPS_PPT / 2; k++) {
            px2[k] = pack2f(sx[2 * k], sx[2 * k + 1]);
            py2[k] = pack2f(sy[2 * k], sy[2 * k + 1]);
            pz2[k] = pack2f(sz[2 * k], sz[2 * k + 1]);
        }
    }
    const bool valid9 = (t + 9 * FT) < FPS_PPC;        // only j=9 can be invalid

    const uint32_t slot_base = smem_u32(&s_slots[0][0]);
    const uint32_t mbar_base = smem_u32(&s_mbar[0]);
    if (t == 0) { mbar_init(mbar_base, 1); mbar_init(mbar_base + 8, 1); }

    const unsigned s_idx = cta * FPS_WARPS + (unsigned)warp;
    uint32_t rk[2] = {0, 0}, rm[2] = {0, 0};
    if (lane < FPS_CTAS) {
        uint32_t soff = s_idx * SLOT_BYTES;
        rk[0] = mapa_u32(slot_base + soff, (uint32_t)lane);
        rk[1] = mapa_u32(slot_base + FPS_SLOTS * SLOT_BYTES + soff, (uint32_t)lane);
        rm[0] = mapa_u32(mbar_base, (uint32_t)lane);
        rm[1] = mapa_u32(mbar_base + 8u, (uint32_t)lane);
    }

    asm volatile("barrier.cluster.arrive.aligned;" ::: "memory");
    asm volatile("barrier.cluster.wait.aligned;" ::: "memory");

    float lx, ly, lz;
    {
        float4 P0 = g_p4[0];
        lx = P0.x; ly = P0.y; lz = P0.z;
        if (cta == 0 && t == 0) {
            out_np[0] = P0.x; out_np[1] = P0.y; out_np[2] = P0.z;
            g_q4[0] = P0;
        }
    }

    unsigned ph0 = 0, ph1 = 0;

    for (int i = 1; i < Msamp; i++) {
        // --- packed update: dx = px + (-lx) (IEEE identity with px - lx) ---
        const unsigned long long nlx2 = pack2f(-lx, -lx);
        const unsigned long long nly2 = pack2f(-ly, -ly);
        const unsigned long long nlz2 = pack2f(-lz, -lz);
        unsigned bd = 0, bi = 0x7FFFFFFFu;
#pragma unroll
        for (int k = 0; k < FPS_PPT / 2; k++) {
            unsigned long long dx = f2_add(px2[k], nlx2);
            unsigned long long dy = f2_add(py2[k], nly2);
            unsigned long long dz = f2_add(pz2[k], nlz2);
            unsigned long long xx = f2_mul(dx, dx);
            unsigned long long yy = f2_mul(dy, dy);
            unsigned long long zz = f2_mul(dz, dz);
            unsigned long long s  = f2_add(f2_add(xx, yy), zz);   // ((x^2+y^2)+z^2)
            float d0 = __uint_as_float((unsigned)s);
            float d1 = __uint_as_float((unsigned)(s >> 32));
            float nd0 = fminf(dist[2 * k], d0);
            dist[2 * k] = nd0;
            unsigned db0 = __float_as_uint(nd0);
            if (db0 > bd) { bd = db0; bi = C + (unsigned)(2 * k) * FT; }
            float nd1 = fminf(dist[2 * k + 1], d1);
            dist[2 * k + 1] = nd1;
            unsigned db1 = __float_as_uint(nd1);
            if ((k < 4 || valid9) && db1 > bd) { bd = db1; bi = C + (unsigned)(2 * k + 1) * FT; }
        }
        // --- warp argmax: max dist, tie -> min global index (verified law) ---
        unsigned dmax = __reduce_max_sync(0xFFFFFFFFu, bd);
        bool cand = (bd == dmax);
        unsigned idxmin = __reduce_min_sync(0xFFFFFFFFu, cand ? bi : 0xFFFFFFFFu);
        unsigned long long key =
            ((unsigned long long)dmax << 15) | (unsigned)((32767u - idxmin) & 0x7FFFu);

        // coords of this warp's winner: uniform-address L1 broadcast (slice is L1-resident)
        float4 Pw = __ldg(&g_p4[idxmin]);

        const int buf = i & 1;
        if (lane < FPS_CTAS) {
            uint32_t rs = rk[buf], rmm = rm[buf];
            st_async_u64(rs,      key,                  rmm);
            st_async_u64(rs + 8,  pack2f(Pw.x, Pw.y),   rmm);
            st_async_u64(rs + 16, pack2f(Pw.z, Pw.w),   rmm);
        }
        if (t == 0)
            mbar_expect_tx(mbar_base + 8u * (unsigned)buf, FPS_SLOTS * SLOT_BYTES);

        // --- wait for all 64 slot triplets ---
        unsigned myph = buf ? ph1 : ph0;
        mbar_wait_parity(mbar_base + 8u * (unsigned)buf, myph);
        if (buf) ph1 ^= 1; else ph0 ^= 1;

        // --- cross-slot argmax on keys ---
        unsigned long long wkey;
        int sl = slot_reduce(s_slots[buf], lane, wkey);
        unsigned long long wxy = s_slots[buf][sl * 3 + 1];
        unsigned long long wzw = s_slots[buf][sl * 3 + 2];
        lx = __uint_as_float((unsigned)wxy);
        ly = __uint_as_float((unsigned)(wxy >> 32));
        lz = __uint_as_float((unsigned)wzw);
        if (cta == 0 && t == 0) {
            float w = __uint_as_float((unsigned)(wzw >> 32));
            out_np[3 * i] = lx; out_np[3 * i + 1] = ly; out_np[3 * i + 2] = lz;
            g_q4[i] = make_float4(lx, ly, lz, w);
        }
    }
    // trailing cluster barrier: no CTA exits with peers' st.async in flight
    asm volatile("barrier.cluster.arrive.aligned;" ::: "memory");
    asm volatile("barrier.cluster.wait.aligned;" ::: "memory");
}

// ---------------- kNN: warp scans 2 queries per pass (verified) ----------------
#define INFKEY 0xFFFFFFFFFFFFFFFFull

__device__ __forceinline__ void knn_merge(unsigned long long* cand, int lane,
                                          unsigned long long& cur,
                                          unsigned long long& thr, int& cnt) {
    if (lane < 16) cand[64 + lane] = cur;
#pragma unroll
    for (int s = lane; s < 64; s += 32) if (s >= cnt) cand[s] = INFKEY;
    __syncwarp();
    unsigned long long picked = INFKEY, last = INFKEY;
#pragma unroll 1
    for (int r = 0; r < 16; r++) {
        unsigned long long a = cand[lane];
        unsigned long long b = cand[lane + 32];
        unsigned long long c = (lane < 16) ? cand[64 + lane] : INFKEY;
        unsigned long long v = a < b ? a : b;
        v = v < c ? v : c;
#pragma unroll
        for (int off = 16; off; off >>= 1) {
            unsigned long long o = __shfl_down_sync(0xFFFFFFFFu, v, off);
            if (o < v) v = o;
        }
        v = __shfl_sync(0xFFFFFFFFu, v, 0);
        if (a == v)                       cand[lane]      = INFKEY;
        else if (b == v)                  cand[lane + 32] = INFKEY;
        else if (lane < 16 && c == v)     cand[64 + lane] = INFKEY;
        __syncwarp();
        if (lane == r) picked = v;
        last = v;
    }
    cur = picked; thr = last; cnt = 0;
    __syncwarp();
}

__global__ __launch_bounds__(128) void knn_kernel() {
    __shared__ unsigned long long cand_s[4][KNN_QPW][80];
    const int warp = threadIdx.x >> 5, lane = threadIdx.x & 31;
    const int m0 = (blockIdx.x * 4 + warp) * KNN_QPW;

    float4 Q0 = g_q4[m0], Q1 = g_q4[m0 + 1];
    unsigned long long cur0 = INFKEY, thr0 = INFKEY;
    unsigned long long cur1 = INFKEY, thr1 = INFKEY;
    int cnt0 = 0, cnt1 = 0;
    unsigned long long* c0 = cand_s[warp][0];
    unsigned long long* c1 = cand_s[warp][1];

#pragma unroll 1
    for (int s = 0; s < Npts / 32; s++) {
        int idx = lane + 32 * s;
        float4 P = __ldg(&g_p4[idx]);
        // reference: qq - 2*(q@p.T) + pp, dot as XLA fma chain (verified)
        float dot0 = __fmaf_rn(Q0.z, P.z, __fmaf_rn(Q0.y, P.y, __fmul_rn(Q0.x, P.x)));
        float d0 = __fadd_rn(__fsub_rn(Q0.w, __fmul_rn(2.0f, dot0)), P.w);
        float dot1 = __fmaf_rn(Q1.z, P.z, __fmaf_rn(Q1.y, P.y, __fmul_rn(Q1.x, P.x)));
        float d1 = __fadd_rn(__fsub_rn(Q1.w, __fmul_rn(2.0f, dot1)), P.w);
        unsigned u0 = __float_as_uint(d0);
        u0 ^= (u0 >> 31) ? 0xFFFFFFFFu : 0x80000000u;
        unsigned u1 = __float_as_uint(d1);
        u1 ^= (u1 >> 31) ? 0xFFFFFFFFu : 0x80000000u;
        unsigned long long k0 = ((unsigned long long)u0 << 32) | (unsigned)idx;
        unsigned long long k1 = ((unsigned long long)u1 << 32) | (unsigned)idx;

        bool p0 = k0 < thr0;
        unsigned b0 = __ballot_sync(0xFFFFFFFFu, p0);
        if (p0) c0[cnt0 + __popc(b0 & ((1u << lane) - 1u))] = k0;
        cnt0 += __popc(b0);
        if (cnt0 >= 32) knn_merge(c0, lane, cur0, thr0, cnt0);

        bool p1 = k1 < thr1;
        unsigned b1 = __ballot_sync(0xFFFFFFFFu, p1);
        if (p1) c1[cnt1 + __popc(b1 & ((1u << lane) - 1u))] = k1;
        cnt1 += __popc(b1);
        if (cnt1 >= 32) knn_merge(c1, lane, cur1, thr1, cnt1);
    }
    if (cnt0 > 0) knn_merge(c0, lane, cur0, thr0, cnt0);
    if (cnt1 > 0) knn_merge(c1, lane, cur1, thr1, cnt1);
    if (lane < 16) {
        g_nidx[m0 * KNN + lane]       = (int)(unsigned)(cur0 & 0xFFFFFFFFull);
        g_nidx[(m0 + 1) * KNN + lane] = (int)(unsigned)(cur1 & 0xFFFFFFFFull);
    }
}

// ---------------- gather + linear (GM samples/block); max/min of h + BN partials ----------------
__global__ __launch_bounds__(128) void gemm_kernel(const float* __restrict__ x,
                                                   const float* __restrict__ W) {
    __shared__ float sW[FDIM * COUT];
    __shared__ float sF[GM * KNN][FDIM + 1];
    const int m0 = blockIdx.x * GM, t = threadIdx.x;

    for (int i = t; i < FDIM * COUT; i += 128) sW[i] = W[i];
    for (int e = t; e < GM * KNN * FDIM; e += 128) {
        int mm = e / (KNN * FDIM);
        int rem = e - mm * (KNN * FDIM);
        int r = rem / FDIM, j = rem - r * FDIM;
        int m = m0 + mm;
        int n = g_nidx[m * KNN + r];
        float v;
        if (j < 3) {
            float4 P = g_p4[n];
            float4 Q = g_q4[m];
            v = (j == 0) ? __fsub_rn(P.x, Q.x) : (j == 1) ? __fsub_rn(P.y, Q.y)
                                                          : __fsub_rn(P.z, Q.z);
        } else {
            v = __ldg(&x[n * CIN + (j - 3)]);
        }
        sF[mm * KNN + r][j] = v;
    }
    __syncthreads();

#pragma unroll 1
    for (int mm = 0; mm < GM; mm++) {
        float acc[KNN];
#pragma unroll
        for (int r = 0; r < KNN; r++) acc[r] = 0.0f;
#pragma unroll 1
        for (int j = 0; j < FDIM; j++) {
            float wv = sW[j * COUT + t];
#pragma unroll
            for (int r = 0; r < KNN; r++)
                acc[r] = fmaf(sF[mm * KNN + r][j], wv, acc[r]);
        }
        float s1 = 0.0f, s2 = 0.0f;
        float mx = acc[0], mn = acc[0];
#pragma unroll
        for (int r = 0; r < KNN; r++) {
            s1 += acc[r];
            s2 = fmaf(acc[r], acc[r], s2);
            mx = fmaxf(mx, acc[r]);
            mn = fminf(mn, acc[r]);
        }
        const int m = m0 + mm;
        g_maxh[m * COUT + t] = mx;
        g_minh[m * COUT + t] = mn;
        g_ps [m * COUT + t] = s1;
        g_pss[m * COUT + t] = s2;
    }
}

// ---------------- deterministic BN stats reduction ----------------
__global__ __launch_bounds__(256) void stats_kernel() {
    __shared__ float s1[256], s2[256];
    const int c = blockIdx.x, t = threadIdx.x;
    float a = 0.0f, b = 0.0f;
    for (int m = t; m < Msamp; m += 256) {
        a += g_ps [m * COUT + c];
        b += g_pss[m * COUT + c];
    }
    s1[t] = a; s2[t] = b;
    __syncthreads();
    for (int o = 128; o; o >>= 1) {
        if (t < o) { s1[t] += s1[t + o]; s2[t] += s2[t + o]; }
        __syncthreads();
    }
    if (t == 0) {
        const float inv_n = 1.0f / (float)(Msamp * KNN);
        float mean = s1[0] * inv_n;
        float var  = fmaxf(s2[0] * inv_n - mean * mean, 0.0f);
        g_mean[c] = mean;
        g_rstd[c] = rsqrtf(var + BN_EPS);
    }
}

// ---------------- BN + ReLU + maxpool (exact via per-channel monotonicity) ----------------
__global__ __launch_bounds__(128) void final_kernel(const float* __restrict__ gamma,
                                                    const float* __restrict__ beta,
                                                    float* __restrict__ out_x,
                                                    float* __restrict__ out_no) {
    const int m = blockIdx.x, c = threadIdx.x;
    const float mean = g_mean[c], inv = g_rstd[c];
    const float gm = __ldg(&gamma[c]), bt = __ldg(&beta[c]);
    float h = (gm >= 0.0f) ? g_maxh[m * COUT + c] : g_minh[m * COUT + c];
    float y = fmaxf((h - mean) * inv * gm + bt, 0.0f);
    out_x[m * COUT + c] = y;
    if (out_no != nullptr && m == 0 && c == 0) *out_no = (float)Msamp;
}

// ---------------- launch ----------------
extern "C" void kernel_launch(void* const* d_in, const int* in_sizes, int n_in,
                              void* d_out, int out_size) {
    const float* p     = (const float*)d_in[0];
    const float* x     = (const float*)d_in[1];
    const float* W     = (const float*)d_in[3];
    const float* gamma = (const float*)d_in[4];
    const float* beta  = (const float*)d_in[5];
    float* out = (float*)d_out;

    const int np_elems = Msamp * 3;
    const int x_elems  = Msamp * COUT;

    float* np_dst = out;
    float* x_dst  = out + np_elems;
    float* no_dst = nullptr;
    if (out_size >= np_elems + x_elems + 1) {
        no_dst = out + np_elems + x_elems;
    } else if (out_size == x_elems) {
        float* scr; cudaGetSymbolAddress((void**)&scr, g_np_scratch);
        np_dst = scr;
        x_dst  = out;
    }

    pack_kernel <<<(Npts + 255) / 256, 256>>>(p);
    fps_kernel  <<<FPS_CTAS, FT>>>(np_dst);
    knn_kernel  <<<Msamp / (4 * KNN_QPW), 128>>>();
    gemm_kernel <<<Msamp / GM, 128>>>(x, W);
    stats_kernel<<<COUT, 256>>>();
    final_kernel<<<Msamp, 128>>>(gamma, beta, x_dst, no_dst);
}